// round 8
// baseline (speedup 1.0000x reference)
#include <cuda_runtime.h>
#include <math.h>

// FNetBlock: B=4, L=512, D=64, LAG=32  (2048 rows)
// out[row,d] = b0 + c[row,d] * (c>0 ? A_pos[row] : A_neg[row])
//   c[row,d] = sum_e x[row,e] cos(2*pi*d*e/64)
//   m[row,f] = sum_j mask[row,j] cos(2*pi*f*j/512), f=0..256
//   s = sort(m);  A_pos = sum_k W[k] s[k]      + W[32+k] s[225+k]
//                 A_neg = sum_k W[k] s[256-k]  + W[32+k] s[31-k]
// Two radix-2 folds -> 64-term per-thread DFT with COMPILE-TIME cosine
// tables (constexpr double Taylor, exact pi*n/256 reduction) -> inner loop
// is pure MAC: 1 LDG.128 (table) + 1 LDS.128 (data) + 4 FFMA per 2 terms.
// Bottom/top-32 via register bitonic selection (validated unchanged).

struct alignas(16) F4h { float x, y, z, w; };
struct TabChunk { F4h v[1024]; };

// cos(pi * n / 256), exact range reduction, double Taylor on [0, pi/2]
constexpr double dcospi(long long n) {
    long long m = n % 512; if (m < 0) m += 512;
    double sign = 1.0;
    if (m > 256) m = 512 - m;
    if (m > 128) { sign = -1.0; m = 256 - m; }
    double x = 3.14159265358979323846 * (double)m / 256.0;  // [0, pi/2]
    double x2 = x * x;
    double t = 1.0, s = 1.0;
    for (int k = 1; k <= 10; ++k) {
        t *= -x2 / (double)((2 * k - 1) * (2 * k));
        s += t;
    }
    return sign * s;
}
constexpr float fcospi(long long n) { return (float)dcospi(n); }

// DFT table: entry [g][f] = (cos(2g*phi_f), cos(psi_f+2g*phi_f),
//                            cos((2g+1)*phi_f), cos(psi_f+(2g+1)*phi_f))
// phi_f = 2pi f/256 -> cos(a*phi_f) = cospi(2af/256); psi_f+a*phi_f -> (2a+1)f
template<int C> constexpr TabChunk make_dft_chunk() {
    TabChunk t{};
    for (int gl = 0; gl < 8; ++gl)
        for (int f = 0; f < 128; ++f) {
            long long a0 = 2LL * (C * 8 + gl), a1 = a0 + 1;
            t.v[gl * 128 + f] = F4h{ fcospi(2 * a0 * f), fcospi((2 * a0 + 1) * f),
                                     fcospi(2 * a1 * f), fcospi((2 * a1 + 1) * f) };
        }
    return t;
}
// x table: entry [h][d] = cos(2pi*d*(4h+i)/64) = cospi(8*d*(4h+i)/256), i=0..3
constexpr TabChunk make_x_chunk() {
    TabChunk t{};
    for (int h = 0; h < 16; ++h)
        for (int d = 0; d < 64; ++d)
            t.v[h * 64 + d] = F4h{ fcospi(8LL * (4 * h + 0) * d), fcospi(8LL * (4 * h + 1) * d),
                                   fcospi(8LL * (4 * h + 2) * d), fcospi(8LL * (4 * h + 3) * d) };
    return t;
}

__device__ const TabChunk g_dft0 = make_dft_chunk<0>();
__device__ const TabChunk g_dft1 = make_dft_chunk<1>();
__device__ const TabChunk g_dft2 = make_dft_chunk<2>();
__device__ const TabChunk g_dft3 = make_dft_chunk<3>();
__device__ const TabChunk g_xt   = make_x_chunk();

__global__ __launch_bounds__(128) void fnet_kernel(
    const float* __restrict__ x,     // [2048, 64]
    const float* __restrict__ mask,  // [2048, 512]
    const float* __restrict__ W,     // [64]
    const float* __restrict__ bvec,  // [1]
    float* __restrict__ out)         // [2048, 64]
{
    __shared__ float  sb[512];                    // mask row (u)
    __shared__ __align__(16) float2 foldP[2][68]; // [parity][a] = (we, wo)
    __shared__ __align__(16) float xs[64];
    __shared__ float  slow[4][32];
    __shared__ float  shigh[4][32];
    __shared__ float  mbuf[4][32];
    __shared__ float  sm128;
    __shared__ float  sPP[2], sPN[2];

    const int tid  = threadIdx.x;     // 0..127
    const int lane = tid & 31;
    const int wr   = tid >> 5;        // warp 0..3
    const int row  = blockIdx.x;
    const int f    = tid;

    // ---- coalesced vectorized loads ----
    {
        const float4* m4 = (const float4*)(mask + row * 512);
        ((float4*)sb)[tid] = m4[tid];
    }
    if (tid < 16) {
        const float4* x4 = (const float4*)(x + row * 64);
        ((float4*)xs)[tid] = x4[tid];
    }
    __syncthreads();

    // ---- double fold: we_p[a], wo_p[a], a=0..63, parity p; s=(-1)^p ----
    {
        const int pp = tid >> 6;
        const int a  = tid & 63;
        const float s = pp ? -1.0f : 1.0f;
        const float* u = sb;
        float we, wo;
        if (a == 0) {
            we = fmaf(s, u[256], u[0]);
            wo = (u[1] + u[511]) + s * (u[255] + u[257]);
        } else {
            we = (u[2*a] + u[512-2*a]) + s * (u[256-2*a] + u[256+2*a]);
            wo = (u[2*a+1] + u[511-2*a]) + s * (u[255-2*a] + u[257+2*a]);
        }
        foldP[pp][a] = make_float2(we, wo);
    }
    __syncthreads();

    // ---- folded DFT: 64 terms, table-driven pure MAC ----
    const int p = f & 1;
    float E0 = 0.f, O0 = 0.f, E1 = 0.f, O1 = 0.f;
    const float4* wq = (const float4*)&foldP[p][0];   // (we,wo) x2 per load
    #pragma unroll
    for (int g = 0; g < 32; ++g) {
        const F4h* tp = (g < 8)  ? &g_dft0.v[g * 128 + f]
                      : (g < 16) ? &g_dft1.v[(g - 8) * 128 + f]
                      : (g < 24) ? &g_dft2.v[(g - 16) * 128 + f]
                                 : &g_dft3.v[(g - 24) * 128 + f];
        float4 T = __ldg(reinterpret_cast<const float4*>(tp));
        float4 q = wq[g];
        E0 = fmaf(q.x, T.x, E0);  O0 = fmaf(q.y, T.y, O0);
        E1 = fmaf(q.z, T.z, E1);  O1 = fmaf(q.w, T.w, O1);
    }
    float E = E0 + E1;
    float O = O0 + O1;
    if (p == 0) {                      // tail: v_e[64]*cos(pi*f/2)
        float t64 = sb[128] + sb[384];
        E += (f & 2) ? -t64 : t64;
    }
    float v0 = E + O;    // m[f]
    float v1 = E - O;    // m[256-f]

    // ---- m[128] = sum_b u[4b] - u[4b+2], by warp 3 ----
    if (wr == 3) {
        float s = 0.f;
        #pragma unroll
        for (int q = 0; q < 4; q++) {
            int b = lane + q * 32;
            s += sb[4*b] - sb[4*b+2];
        }
        #pragma unroll
        for (int o = 16; o; o >>= 1) s += __shfl_xor_sync(0xffffffffu, s, o);
        if (lane == 0) sm128 = s;
    }

    // ---- warp bitonic sort of 64 (2 regs/lane), ascending ----
    #pragma unroll
    for (int k = 2; k <= 32; k <<= 1) {
        #pragma unroll
        for (int j = k >> 1; j > 0; j >>= 1) {
            bool up0 = ((lane & k) == 0);
            bool up1 = (((lane + 32) & k) == 0);
            float p0 = __shfl_xor_sync(0xffffffffu, v0, j);
            float p1 = __shfl_xor_sync(0xffffffffu, v1, j);
            bool low = ((lane & j) == 0);
            v0 = (low == up0) ? fminf(v0, p0) : fmaxf(v0, p0);
            v1 = (low == up1) ? fminf(v1, p1) : fmaxf(v1, p1);
        }
    }
    {   // k = 64 stage: j=32 crosses regs, then clean
        float lo = fminf(v0, v1), hi = fmaxf(v0, v1);
        v0 = lo; v1 = hi;
        #pragma unroll
        for (int j = 16; j > 0; j >>= 1) {
            float p0 = __shfl_xor_sync(0xffffffffu, v0, j);
            float p1 = __shfl_xor_sync(0xffffffffu, v1, j);
            bool low = ((lane & j) == 0);
            v0 = low ? fminf(v0, p0) : fmaxf(v0, p0);
            v1 = low ? fminf(v1, p1) : fmaxf(v1, p1);
        }
    }
    slow [wr][lane] = v0;   // bottom 32 ascending
    shigh[wr][lane] = v1;   // top 32 ascending
    __syncthreads();

    // ---- level-1 merges (keep 32 extremes of 64) ----
    {
        float res;
        if      (wr == 0) res = fminf(slow [0][lane], slow [1][31-lane]);
        else if (wr == 1) res = fminf(slow [2][lane], slow [3][31-lane]);
        else if (wr == 2) res = fmaxf(shigh[0][lane], shigh[1][31-lane]);
        else              res = fmaxf(shigh[2][lane], shigh[3][31-lane]);
        #pragma unroll
        for (int j = 16; j > 0; j >>= 1) {   // bitonic clean -> ascending
            float pv = __shfl_xor_sync(0xffffffffu, res, j);
            res = ((lane & j) == 0) ? fminf(res, pv) : fmaxf(res, pv);
        }
        mbuf[wr][lane] = res;
    }
    __syncthreads();

    // ---- final merges + m128 insert + epilogue dot  |  x-transform ----
    float cval = 0.f;
    if (wr == 0) {
        float lowv = fminf(mbuf[0][lane], mbuf[1][31-lane]);
        #pragma unroll
        for (int j = 16; j > 0; j >>= 1) {
            float pv = __shfl_xor_sync(0xffffffffu, lowv, j);
            lowv = ((lane & j) == 0) ? fminf(lowv, pv) : fmaxf(lowv, pv);
        }
        float m128 = sm128;
        unsigned bal = __ballot_sync(0xffffffffu, lowv < m128);
        int cnt = __popc(bal);
        float sh = __shfl_up_sync(0xffffffffu, lowv, 1);
        if (lane >= cnt) lowv = (lane == cnt) ? m128 : sh;
        float pp = __ldg(&W[lane])      * lowv;
        float pn = __ldg(&W[63 - lane]) * lowv;
        #pragma unroll
        for (int o = 16; o; o >>= 1) {
            pp += __shfl_xor_sync(0xffffffffu, pp, o);
            pn += __shfl_xor_sync(0xffffffffu, pn, o);
        }
        if (lane == 0) { sPP[0] = pp; sPN[0] = pn; }
    } else if (wr == 1) {
        float highv = fmaxf(mbuf[2][lane], mbuf[3][31-lane]);
        #pragma unroll
        for (int j = 16; j > 0; j >>= 1) {
            float pv = __shfl_xor_sync(0xffffffffu, highv, j);
            highv = ((lane & j) == 0) ? fminf(highv, pv) : fmaxf(highv, pv);
        }
        float m128 = sm128;
        unsigned bal = __ballot_sync(0xffffffffu, highv < m128);
        int cnt = __popc(bal);
        float shd = __shfl_down_sync(0xffffffffu, highv, 1);
        highv = (lane + 1 < cnt) ? shd : ((lane + 1 == cnt) ? m128 : highv);
        float pp = __ldg(&W[32 + lane]) * highv;
        float pn = __ldg(&W[31 - lane]) * highv;
        #pragma unroll
        for (int o = 16; o; o >>= 1) {
            pp += __shfl_xor_sync(0xffffffffu, pp, o);
            pn += __shfl_xor_sync(0xffffffffu, pn, o);
        }
        if (lane == 0) { sPP[1] = pp; sPN[1] = pn; }
    } else {
        // 64-point cosine transform of x, table-driven
        int d = tid - 64;
        float ca = 0.f, cb = 0.f;
        #pragma unroll
        for (int h = 0; h < 16; ++h) {
            float4 T  = __ldg(reinterpret_cast<const float4*>(&g_xt.v[h * 64 + d]));
            float4 xv = ((const float4*)xs)[h];    // broadcast
            ca = fmaf(xv.x, T.x, ca);  cb = fmaf(xv.y, T.y, cb);
            ca = fmaf(xv.z, T.z, ca);  cb = fmaf(xv.w, T.w, cb);
        }
        cval = ca + cb;
    }
    __syncthreads();

    // ---- output (warps 2,3; coalesced) ----
    if (wr >= 2) {
        int d = tid - 64;
        float Ap = sPP[0] + sPP[1];
        float An = sPN[0] + sPN[1];
        float A = (cval > 0.f) ? Ap : An;
        out[row * 64 + d] = fmaf(cval, A, bvec[0]);
    }
}

extern "C" void kernel_launch(void* const* d_in, const int* in_sizes, int n_in,
                              void* d_out, int out_size) {
    const float* x    = (const float*)d_in[0];
    const float* mask = (const float*)d_in[1];
    const float* W    = (const float*)d_in[2];
    const float* b    = (const float*)d_in[3];
    fnet_kernel<<<2048, 128>>>(x, mask, W, b, (float*)d_out);
}

// round 9
// speedup vs baseline: 1.5788x; 1.5788x over previous
#include <cuda_runtime.h>
#include <math.h>

// FNetBlock: B=4, L=512, D=64, LAG=32  (2048 rows)
// out[row,d] = b0 + c[row,d] * (c>0 ? A_pos[row] : A_neg[row])
//   c[row,d] = sum_e x[row,e] cos(2*pi*d*e/64)
//   m[row,f] = sum_j mask[row,j] cos(2*pi*f*j/512), f=0..256
//   s = sort(m);  A_pos = sum_k W[k] s[k]      + W[32+k] s[225+k]
//                 A_neg = sum_k W[k] s[256-k]  + W[32+k] s[31-k]
// 2 rows/block, 128 threads: each thread runs the 64-term folded DFT for
// BOTH rows sharing one set of packed f32x2 Chebyshev chains (fma.rn.f32x2
// = FFMA2). Dual register-bitonic sorts interleaved for ILP. Packed
// x-transform. Bottom/top-32 selection identical to validated R7 network.

typedef unsigned long long u64t;
__device__ __forceinline__ u64t pk2(float lo, float hi) {
    u64t r; asm("mov.b64 %0,{%1,%2};" : "=l"(r) : "f"(lo), "f"(hi)); return r;
}
__device__ __forceinline__ void upk2(float& lo, float& hi, u64t v) {
    asm("mov.b64 {%0,%1},%2;" : "=f"(lo), "=f"(hi) : "l"(v));
}
__device__ __forceinline__ u64t fma2_(u64t a, u64t b, u64t c) {
    u64t d; asm("fma.rn.f32x2 %0,%1,%2,%3;" : "=l"(d) : "l"(a), "l"(b), "l"(c)); return d;
}
__device__ __forceinline__ u64t mul2_(u64t a, u64t b) {
    u64t d; asm("mul.rn.f32x2 %0,%1,%2;" : "=l"(d) : "l"(a), "l"(b)); return d;
}
__device__ __forceinline__ u64t add2_(u64t a, u64t b) {
    u64t d; asm("add.rn.f32x2 %0,%1,%2;" : "=l"(d) : "l"(a), "l"(b)); return d;
}

__global__ __launch_bounds__(128) void fnet_kernel(
    const float* __restrict__ x,     // [2048, 64]
    const float* __restrict__ mask,  // [2048, 512]
    const float* __restrict__ W,     // [64]
    const float* __restrict__ bvec,  // [1]
    float* __restrict__ out)         // [2048, 64]
{
    __shared__ float  sb[2][512];                       // mask rows (u)
    __shared__ __align__(16) float2 foldP[2][2][68];    // [row][parity][a]=(we,wo)
    __shared__ __align__(16) float  xs[2][64];
    __shared__ float  slow[2][4][32];
    __shared__ float  shigh[2][4][32];
    __shared__ float  mbuf[2][4][32];
    __shared__ float  sm128[2];
    __shared__ float  sPP[2][2], sPN[2][2];

    const int tid  = threadIdx.x;     // 0..127
    const int lane = tid & 31;
    const int wr   = tid >> 5;        // warp 0..3
    const int row0 = blockIdx.x * 2;

    // ---- trig early (independent of smem; hides MUFU behind load wait) ----
    const int f = tid;
    float cphi, sphi, cpsi, spsi;
    sincospif((float)f * (1.0f/128.0f), &sphi, &cphi);  // phi = 2*pi*f/256
    sincospif((float)f * (1.0f/256.0f), &spsi, &cpsi);  // psi = pi*f/256

    // ---- coalesced vectorized loads (2 rows) ----
    {
        const float4* m4 = (const float4*)(mask + row0 * 512);
        ((float4*)sb)[tid]       = m4[tid];
        ((float4*)sb)[tid + 128] = m4[tid + 128];
    }
    if (tid < 32) {
        const float4* x4 = (const float4*)(x + row0 * 64);
        ((float4*)xs)[tid] = x4[tid];
    }
    __syncthreads();

    // ---- double fold per row: we_p[a], wo_p[a], a=0..63; s=(-1)^p ----
    {
        const int pp = tid >> 6;
        const int a  = tid & 63;
        const float s = pp ? -1.0f : 1.0f;
        #pragma unroll
        for (int rr = 0; rr < 2; rr++) {
            const float* u = sb[rr];
            float we, wo;
            if (a == 0) {
                we = fmaf(s, u[256], u[0]);
                wo = (u[1] + u[511]) + s * (u[255] + u[257]);
            } else {
                we = (u[2*a] + u[512-2*a]) + s * (u[256-2*a] + u[256+2*a]);
                wo = (u[2*a+1] + u[511-2*a]) + s * (u[255-2*a] + u[257+2*a]);
            }
            foldP[rr][pp][a] = make_float2(we, wo);
        }
    }
    __syncthreads();

    // ---- folded DFT for BOTH rows, packed f32x2 chains shared ----
    const int p = f & 1;
    const float c2 = fmaf(2.0f*cphi, cphi, -1.0f);      // cos(2phi)
    const float s2 = 2.0f * sphi * cphi;                // sin(2phi)
    const float wpe0 = fmaf(cpsi, c2,  spsi * s2);      // cos(psi-2phi)
    const float wo0  = fmaf(cpsi, cphi, -(spsi * sphi));// cos(psi+phi)
    const float wpo0 = fmaf(cpsi, cphi,  (spsi * sphi));// cos(psi-phi)

    const u64t NEG1 = pk2(-1.0f, -1.0f);
    const u64t T2   = pk2(2.0f * c2, 2.0f * c2);
    u64t M0  = pk2(1.0f,  cpsi);      // (cos(a*phi) even chain, psi-even chain)
    u64t NP0 = pk2(-c2,  -wpe0);      // negated prevs
    u64t M1  = pk2(cphi,  wo0);       // odd chains
    u64t NP1 = pk2(-cphi, -wpo0);

    u64t A0a = 0, A1a = 0, A0b = 0, A1b = 0;
    const ulonglong2* wqA = (const ulonglong2*)&foldP[0][p][0];
    const ulonglong2* wqB = (const ulonglong2*)&foldP[1][p][0];
    #pragma unroll
    for (int g = 0; g < 32; ++g) {
        ulonglong2 qa = wqA[g];        // (we,wo) for a=2g | a=2g+1
        ulonglong2 qb = wqB[g];
        A0a = fma2_(qa.x, M0, A0a);
        A1a = fma2_(qa.y, M1, A1a);
        A0b = fma2_(qb.x, M0, A0b);
        A1b = fma2_(qb.y, M1, A1b);
        u64t n0 = fma2_(T2, M0, NP0); NP0 = mul2_(M0, NEG1); M0 = n0;
        u64t n1 = fma2_(T2, M1, NP1); NP1 = mul2_(M1, NEG1); M1 = n1;
    }
    float vA0, vA1, vB0, vB1;
    {
        float Ea, Oa, Eb, Ob;
        upk2(Ea, Oa, add2_(A0a, A1a));
        upk2(Eb, Ob, add2_(A0b, A1b));
        if (p == 0) {                  // tail: v_e[64]*cos(pi*f/2)
            float sgn = (f & 2) ? -1.f : 1.f;
            Ea = fmaf(sgn, sb[0][128] + sb[0][384], Ea);
            Eb = fmaf(sgn, sb[1][128] + sb[1][384], Eb);
        }
        vA0 = Ea + Oa;  vA1 = Ea - Oa; // m[f], m[256-f] row A
        vB0 = Eb + Ob;  vB1 = Eb - Ob; // row B
    }

    // ---- m[128] per row: warp3 -> row0, warp2 -> row1 ----
    if (wr >= 2) {
        int rr = 3 - wr;
        const float* u = sb[rr];
        float s = 0.f;
        #pragma unroll
        for (int q = 0; q < 4; q++) {
            int b = lane + q * 32;
            s += u[4*b] - u[4*b+2];
        }
        #pragma unroll
        for (int o = 16; o; o >>= 1) s += __shfl_xor_sync(0xffffffffu, s, o);
        if (lane == 0) sm128[rr] = s;
    }

    // ---- dual warp bitonic sorts of 64 (interleaved for ILP) ----
    #pragma unroll
    for (int k = 2; k <= 32; k <<= 1) {
        #pragma unroll
        for (int j = k >> 1; j > 0; j >>= 1) {
            bool up0 = ((lane & k) == 0);
            bool up1 = (((lane + 32) & k) == 0);
            float pA0 = __shfl_xor_sync(0xffffffffu, vA0, j);
            float pA1 = __shfl_xor_sync(0xffffffffu, vA1, j);
            float pB0 = __shfl_xor_sync(0xffffffffu, vB0, j);
            float pB1 = __shfl_xor_sync(0xffffffffu, vB1, j);
            bool low = ((lane & j) == 0);
            vA0 = (low == up0) ? fminf(vA0, pA0) : fmaxf(vA0, pA0);
            vA1 = (low == up1) ? fminf(vA1, pA1) : fmaxf(vA1, pA1);
            vB0 = (low == up0) ? fminf(vB0, pB0) : fmaxf(vB0, pB0);
            vB1 = (low == up1) ? fminf(vB1, pB1) : fmaxf(vB1, pB1);
        }
    }
    {   // k = 64 stage: j=32 crosses regs, then clean
        float loA = fminf(vA0, vA1), hiA = fmaxf(vA0, vA1);
        float loB = fminf(vB0, vB1), hiB = fmaxf(vB0, vB1);
        vA0 = loA; vA1 = hiA; vB0 = loB; vB1 = hiB;
        #pragma unroll
        for (int j = 16; j > 0; j >>= 1) {
            float pA0 = __shfl_xor_sync(0xffffffffu, vA0, j);
            float pA1 = __shfl_xor_sync(0xffffffffu, vA1, j);
            float pB0 = __shfl_xor_sync(0xffffffffu, vB0, j);
            float pB1 = __shfl_xor_sync(0xffffffffu, vB1, j);
            bool low = ((lane & j) == 0);
            vA0 = low ? fminf(vA0, pA0) : fmaxf(vA0, pA0);
            vA1 = low ? fminf(vA1, pA1) : fmaxf(vA1, pA1);
            vB0 = low ? fminf(vB0, pB0) : fmaxf(vB0, pB0);
            vB1 = low ? fminf(vB1, pB1) : fmaxf(vB1, pB1);
        }
    }
    slow [0][wr][lane] = vA0;   shigh[0][wr][lane] = vA1;
    slow [1][wr][lane] = vB0;   shigh[1][wr][lane] = vB1;
    __syncthreads();

    // ---- level-1 merges (keep 32 extremes of 64), both rows per warp ----
    #pragma unroll
    for (int rr = 0; rr < 2; rr++) {
        float res;
        if      (wr == 0) res = fminf(slow [rr][0][lane], slow [rr][1][31-lane]);
        else if (wr == 1) res = fminf(slow [rr][2][lane], slow [rr][3][31-lane]);
        else if (wr == 2) res = fmaxf(shigh[rr][0][lane], shigh[rr][1][31-lane]);
        else              res = fmaxf(shigh[rr][2][lane], shigh[rr][3][31-lane]);
        #pragma unroll
        for (int j = 16; j > 0; j >>= 1) {   // bitonic clean -> ascending
            float pv = __shfl_xor_sync(0xffffffffu, res, j);
            res = ((lane & j) == 0) ? fminf(res, pv) : fmaxf(res, pv);
        }
        mbuf[rr][wr][lane] = res;
    }
    __syncthreads();

    // ---- final merges + m128 insert + epilogue dots (one task per warp) ----
    {
        int rr = wr >> 1;
        if ((wr & 1) == 0) {      // low side of row rr
            float lowv = fminf(mbuf[rr][0][lane], mbuf[rr][1][31-lane]);
            #pragma unroll
            for (int j = 16; j > 0; j >>= 1) {
                float pv = __shfl_xor_sync(0xffffffffu, lowv, j);
                lowv = ((lane & j) == 0) ? fminf(lowv, pv) : fmaxf(lowv, pv);
            }
            float m128 = sm128[rr];
            unsigned bal = __ballot_sync(0xffffffffu, lowv < m128);
            int cnt = __popc(bal);
            float sh = __shfl_up_sync(0xffffffffu, lowv, 1);
            if (lane >= cnt) lowv = (lane == cnt) ? m128 : sh;
            float pp = __ldg(&W[lane])      * lowv;
            float pn = __ldg(&W[63 - lane]) * lowv;
            #pragma unroll
            for (int o = 16; o; o >>= 1) {
                pp += __shfl_xor_sync(0xffffffffu, pp, o);
                pn += __shfl_xor_sync(0xffffffffu, pn, o);
            }
            if (lane == 0) { sPP[rr][0] = pp; sPN[rr][0] = pn; }
        } else {                  // high side of row rr
            float highv = fmaxf(mbuf[rr][2][lane], mbuf[rr][3][31-lane]);
            #pragma unroll
            for (int j = 16; j > 0; j >>= 1) {
                float pv = __shfl_xor_sync(0xffffffffu, highv, j);
                highv = ((lane & j) == 0) ? fminf(highv, pv) : fmaxf(highv, pv);
            }
            float m128 = sm128[rr];
            unsigned bal = __ballot_sync(0xffffffffu, highv < m128);
            int cnt = __popc(bal);
            float shd = __shfl_down_sync(0xffffffffu, highv, 1);
            highv = (lane + 1 < cnt) ? shd : ((lane + 1 == cnt) ? m128 : highv);
            float pp = __ldg(&W[32 + lane]) * highv;
            float pn = __ldg(&W[31 - lane]) * highv;
            #pragma unroll
            for (int o = 16; o; o >>= 1) {
                pp += __shfl_xor_sync(0xffffffffu, pp, o);
                pn += __shfl_xor_sync(0xffffffffu, pn, o);
            }
            if (lane == 0) { sPP[rr][1] = pp; sPN[rr][1] = pn; }
        }
    }

    // ---- x-transform, packed: thread -> (row tid>>6, d tid&63) ----
    float cval;
    {
        int rr = tid >> 6;
        int d  = tid & 63;
        float cth, sth;
        sincospif((float)d * (1.0f/32.0f), &sth, &cth);  // theta = 2*pi*d/64
        float c2t = fmaf(2.0f*cth, cth, -1.0f);          // cos(2theta)
        u64t Tx  = pk2(2.0f*c2t, 2.0f*c2t);
        u64t P   = pk2(1.0f, cth);                       // (cos(2h t), cos((2h+1)t))
        u64t NPx = pk2(-c2t, -cth);
        u64t acc = 0;
        const u64t* xr = (const u64t*)xs[rr];            // (x[2h], x[2h+1])
        #pragma unroll
        for (int h = 0; h < 32; ++h) {
            acc = fma2_(xr[h], P, acc);
            u64t n = fma2_(Tx, P, NPx); NPx = mul2_(P, NEG1); P = n;
        }
        float ca, cb;
        upk2(ca, cb, acc);
        cval = ca + cb;
    }
    __syncthreads();

    // ---- output: 128 threads -> 128 outputs, coalesced ----
    {
        int rr = tid >> 6;
        int d  = tid & 63;
        float Ap = sPP[rr][0] + sPP[rr][1];
        float An = sPN[rr][0] + sPN[rr][1];
        float A = (cval > 0.f) ? Ap : An;
        out[(row0 + rr) * 64 + d] = fmaf(cval, A, bvec[0]);
    }
}

extern "C" void kernel_launch(void* const* d_in, const int* in_sizes, int n_in,
                              void* d_out, int out_size) {
    const float* x    = (const float*)d_in[0];
    const float* mask = (const float*)d_in[1];
    const float* W    = (const float*)d_in[2];
    const float* b    = (const float*)d_in[3];
    fnet_kernel<<<1024, 128>>>(x, mask, W, b, (float*)d_out);
}